// round 1
// baseline (speedup 1.0000x reference)
#include <cuda_runtime.h>

#define D_MODEL 1024
#define S_LEN   2048
#define NB      2
#define NH      16
#define HD      64
#define DQK     128
#define BHN     (NB*NH)

// Scratch (allocation-free rule: __device__ globals)
__device__ float g_Qp[(size_t)BHN * S_LEN * DQK];   // [bh][s][128]: [0:64]=Q/8, [64:128]=lam*tanh(Q)@J
__device__ float g_Kp[(size_t)BHN * S_LEN * DQK];   // [bh][s][128]: [0:64]=K,   [64:128]=tanh(K)
__device__ float g_Vv[(size_t)BHN * S_LEN * HD];    // [bh][s][64]
__device__ float g_attn[(size_t)NB * S_LEN * D_MODEL]; // attention output, (B,S,D)

enum { LAY_PLAIN = 0, LAY_QK = 1, LAY_V = 2 };

// ---------------------------------------------------------------------------
// C[m,n] = sum_k A[m,k] * W[n,k] + bias[n]   (A: MxK row-major, W: NxK row-major)
// M = 4096, N = 1024, K = 1024. Tile 128x128x8, 256 threads, 8x8 per thread.
// ---------------------------------------------------------------------------
__global__ __launch_bounds__(256) void sgemm_nt(
    const float* __restrict__ A, const float* __restrict__ W,
    const float* __restrict__ bias, float* __restrict__ C, int layout)
{
    __shared__ float As[8][132];
    __shared__ float Ws[8][132];

    const int tid = threadIdx.x;
    const int m0  = blockIdx.y * 128;
    const int n0  = blockIdx.x * 128;
    const int tx  = tid & 15;       // 0..15  -> cols tx*8..+7
    const int ty  = tid >> 4;       // 0..15  -> rows ty*8..+7
    const int lrow = tid >> 1;      // 0..127
    const int lk4  = (tid & 1) << 2; // 0 or 4

    const float* Ap = A + (m0 + lrow) * D_MODEL + lk4;
    const float* Wp = W + (n0 + lrow) * D_MODEL + lk4;

    float acc[8][8];
    #pragma unroll
    for (int i = 0; i < 8; i++)
        #pragma unroll
        for (int j = 0; j < 8; j++) acc[i][j] = 0.f;

    for (int k0 = 0; k0 < D_MODEL; k0 += 8) {
        float4 a = *reinterpret_cast<const float4*>(Ap + k0);
        float4 w = *reinterpret_cast<const float4*>(Wp + k0);
        __syncthreads();
        As[lk4+0][lrow] = a.x; As[lk4+1][lrow] = a.y;
        As[lk4+2][lrow] = a.z; As[lk4+3][lrow] = a.w;
        Ws[lk4+0][lrow] = w.x; Ws[lk4+1][lrow] = w.y;
        Ws[lk4+2][lrow] = w.z; Ws[lk4+3][lrow] = w.w;
        __syncthreads();
        #pragma unroll
        for (int k = 0; k < 8; k++) {
            float4 a0 = *reinterpret_cast<const float4*>(&As[k][ty*8]);
            float4 a1 = *reinterpret_cast<const float4*>(&As[k][ty*8+4]);
            float4 w0 = *reinterpret_cast<const float4*>(&Ws[k][tx*8]);
            float4 w1 = *reinterpret_cast<const float4*>(&Ws[k][tx*8+4]);
            float ar[8] = {a0.x,a0.y,a0.z,a0.w,a1.x,a1.y,a1.z,a1.w};
            float wr[8] = {w0.x,w0.y,w0.z,w0.w,w1.x,w1.y,w1.z,w1.w};
            #pragma unroll
            for (int i = 0; i < 8; i++)
                #pragma unroll
                for (int j = 0; j < 8; j++)
                    acc[i][j] = fmaf(ar[i], wr[j], acc[i][j]);
        }
    }

    float bv[8];
    #pragma unroll
    for (int j = 0; j < 8; j++) bv[j] = bias[n0 + tx*8 + j];

    #pragma unroll
    for (int i = 0; i < 8; i++) {
        const int row = m0 + ty*8 + i;
        #pragma unroll
        for (int j = 0; j < 8; j++) {
            const int col = n0 + tx*8 + j;
            const float v = acc[i][j] + bv[j];
            if (layout == LAY_PLAIN) {
                C[row * D_MODEL + col] = v;
            } else {
                const int b = row >> 11, s = row & 2047;
                const int h = col >> 6,  hd = col & 63;
                if (layout == LAY_QK)
                    C[(((b << 4) + h) * S_LEN + s) * DQK + hd] = v;
                else
                    C[(((b << 4) + h) * S_LEN + s) * HD + hd] = v;
            }
        }
    }
}

// ---------------------------------------------------------------------------
// Per (bh, 64-row chunk): build extended Q' and K'.
//   Q'[r,0:64]   = Q/8           Q'[r,64:128] = lam * tanh(Q[r,:]) @ J_h
//   K'[r,64:128] = tanh(K[r,:])
// ---------------------------------------------------------------------------
__global__ __launch_bounds__(256) void prep_kernel(
    float* __restrict__ Qp, float* __restrict__ Kp,
    const float* __restrict__ J, const float* __restrict__ lam_p)
{
    __shared__ float Js[64 * 65];
    __shared__ float Tq[64 * 65];

    const int bh  = blockIdx.y;
    const int h   = bh & 15;
    const int r0  = blockIdx.x * 64;
    const int tid = threadIdx.x;     // 256
    const float lam = lam_p[0];

    float* Qb = Qp + ((size_t)bh * S_LEN + r0) * DQK;
    float* Kb = Kp + ((size_t)bh * S_LEN + r0) * DQK;
    const float* Jh = J + h * (HD * HD);

    for (int i = tid; i < 4096; i += 256)
        Js[(i >> 6) * 65 + (i & 63)] = Jh[i];

    for (int i = tid; i < 4096; i += 256) {
        const int r = i >> 6, d = i & 63;
        const float q = Qb[r * DQK + d];
        Tq[r * 65 + d] = tanhf(q);
        Qb[r * DQK + d] = q * 0.125f;            // 1/sqrt(64)
        const float kv = Kb[r * DQK + d];
        Kb[r * DQK + 64 + d] = tanhf(kv);
    }
    __syncthreads();

    const int e  = tid & 63;
    const int rb = tid >> 6;  // 0..3
    for (int rr = 0; rr < 16; rr++) {
        const int r = rb * 16 + rr;
        float acc = 0.f;
        #pragma unroll 8
        for (int d = 0; d < 64; d++)
            acc = fmaf(Tq[r * 65 + d], Js[d * 65 + e], acc);
        Qb[r * DQK + 64 + e] = lam * acc;
    }
}

// ---------------------------------------------------------------------------
// Causal flash attention, fp32. d_qk=128, d_v=64. BR=BC=64, 128 threads.
// Thread (ty=tid/16, tx=tid%16) owns 8 rows x 4 cols of the score tile.
// ---------------------------------------------------------------------------
__global__ __launch_bounds__(128) void flash_kernel(
    const float* __restrict__ Qp, const float* __restrict__ Kp,
    const float* __restrict__ V, float* __restrict__ Out)
{
    extern __shared__ float sm[];
    float* Qs = sm;                    // [64][129]
    float* Ks = Qs + 64 * 129;         // [64][129]
    float* Vs = Ks + 64 * 129;         // [64][65]
    float* Ps = Vs + 64 * 65;          // [64][65]

    const int bh  = blockIdx.y;
    const int r0  = blockIdx.x * 64;
    const int tid = threadIdx.x;
    const int ty  = tid >> 4;   // 0..7 -> rows ty*8..+7
    const int tx  = tid & 15;   // cols tx*4..+3

    const float* Qb = Qp + (size_t)bh * S_LEN * DQK;
    const float* Kb = Kp + (size_t)bh * S_LEN * DQK;
    const float* Vb = V  + (size_t)bh * S_LEN * HD;

    for (int i = tid; i < 64 * 128; i += 128) {
        const int r = i >> 7, k = i & 127;
        Qs[r * 129 + k] = Qb[(r0 + r) * DQK + k];
    }

    float m[8], l[8], O[8][4];
    #pragma unroll
    for (int i = 0; i < 8; i++) {
        m[i] = -1e30f; l[i] = 0.f;
        #pragma unroll
        for (int j = 0; j < 4; j++) O[i][j] = 0.f;
    }

    const int ntiles = (r0 >> 6) + 1;
    for (int t = 0; t < ntiles; t++) {
        const int c0 = t * 64;
        __syncthreads();   // previous PV done (also orders first Q use below)
        for (int i = tid; i < 64 * 128; i += 128) {
            const int r = i >> 7, k = i & 127;
            Ks[r * 129 + k] = Kb[(c0 + r) * DQK + k];
        }
        for (int i = tid; i < 64 * 64; i += 128) {
            const int r = i >> 6, d = i & 63;
            Vs[r * 65 + d] = Vb[(c0 + r) * HD + d];
        }
        __syncthreads();

        float s[8][4];
        #pragma unroll
        for (int i = 0; i < 8; i++)
            #pragma unroll
            for (int j = 0; j < 4; j++) s[i][j] = 0.f;

        #pragma unroll 4
        for (int k = 0; k < 128; k++) {
            float kv[4];
            #pragma unroll
            for (int j = 0; j < 4; j++) kv[j] = Ks[(tx*4 + j) * 129 + k];
            #pragma unroll
            for (int i = 0; i < 8; i++) {
                const float q = Qs[(ty*8 + i) * 129 + k];
                #pragma unroll
                for (int j = 0; j < 4; j++) s[i][j] = fmaf(q, kv[j], s[i][j]);
            }
        }

        if (c0 + 63 > r0) {   // only the diagonal tile needs masking
            #pragma unroll
            for (int i = 0; i < 8; i++) {
                const int gi = r0 + ty*8 + i;
                #pragma unroll
                for (int j = 0; j < 4; j++)
                    if (c0 + tx*4 + j > gi) s[i][j] = -1e30f;
            }
        }

        // online softmax update
        #pragma unroll
        for (int i = 0; i < 8; i++) {
            float mx = fmaxf(fmaxf(s[i][0], s[i][1]), fmaxf(s[i][2], s[i][3]));
            mx = fmaxf(mx, __shfl_xor_sync(0xffffffffu, mx, 1, 16));
            mx = fmaxf(mx, __shfl_xor_sync(0xffffffffu, mx, 2, 16));
            mx = fmaxf(mx, __shfl_xor_sync(0xffffffffu, mx, 4, 16));
            mx = fmaxf(mx, __shfl_xor_sync(0xffffffffu, mx, 8, 16));
            const float mn = fmaxf(m[i], mx);
            const float corr = __expf(m[i] - mn);
            m[i] = mn;
            float rs = 0.f;
            #pragma unroll
            for (int j = 0; j < 4; j++) {
                const float p = __expf(s[i][j] - mn);
                s[i][j] = p;
                rs += p;
            }
            rs += __shfl_xor_sync(0xffffffffu, rs, 1, 16);
            rs += __shfl_xor_sync(0xffffffffu, rs, 2, 16);
            rs += __shfl_xor_sync(0xffffffffu, rs, 4, 16);
            rs += __shfl_xor_sync(0xffffffffu, rs, 8, 16);
            l[i] = l[i] * corr + rs;
            #pragma unroll
            for (int j = 0; j < 4; j++) {
                O[i][j] *= corr;
                Ps[(ty*8 + i) * 65 + tx*4 + j] = s[i][j];
            }
        }
        __syncthreads();

        // O += P @ V
        #pragma unroll 4
        for (int j = 0; j < 64; j++) {
            float vv[4];
            #pragma unroll
            for (int c = 0; c < 4; c++) vv[c] = Vs[j * 65 + tx*4 + c];
            #pragma unroll
            for (int i = 0; i < 8; i++) {
                const float p = Ps[(ty*8 + i) * 65 + j];
                #pragma unroll
                for (int c = 0; c < 4; c++) O[i][c] = fmaf(p, vv[c], O[i][c]);
            }
        }
    }

    const int b = bh >> 4, h = bh & 15;
    #pragma unroll
    for (int i = 0; i < 8; i++) {
        const int gr = r0 + ty*8 + i;
        const float inv = 1.f / l[i];
        #pragma unroll
        for (int c = 0; c < 4; c++)
            Out[((size_t)(b * S_LEN + gr)) * D_MODEL + h * HD + tx*4 + c] = O[i][c] * inv;
    }
}

// ---------------------------------------------------------------------------
extern "C" void kernel_launch(void* const* d_in, const int* in_sizes, int n_in,
                              void* d_out, int out_size)
{
    const float* x   = (const float*)d_in[0];
    const float* Wq  = (const float*)d_in[1];
    const float* bq  = (const float*)d_in[2];
    const float* Wk  = (const float*)d_in[3];
    const float* bk  = (const float*)d_in[4];
    const float* Wv  = (const float*)d_in[5];
    const float* bv  = (const float*)d_in[6];
    const float* Wo  = (const float*)d_in[7];
    const float* bo  = (const float*)d_in[8];
    const float* J   = (const float*)d_in[9];
    const float* lam = (const float*)d_in[10];
    float* out = (float*)d_out;

    float *qp, *kp, *vp, *ap;
    cudaGetSymbolAddress((void**)&qp, g_Qp);
    cudaGetSymbolAddress((void**)&kp, g_Kp);
    cudaGetSymbolAddress((void**)&vp, g_Vv);
    cudaGetSymbolAddress((void**)&ap, g_attn);

    const dim3 gg(D_MODEL / 128, (NB * S_LEN) / 128);   // (8, 32)
    sgemm_nt<<<gg, 256>>>(x, Wq, bq, qp, LAY_QK);
    sgemm_nt<<<gg, 256>>>(x, Wk, bk, kp, LAY_QK);
    sgemm_nt<<<gg, 256>>>(x, Wv, bv, vp, LAY_V);

    prep_kernel<<<dim3(S_LEN / 64, BHN), 256>>>(qp, kp, J, lam);

    const int FSMEM = (64 * 129 * 2 + 64 * 65 * 2) * (int)sizeof(float); // 99328 B
    cudaFuncSetAttribute(flash_kernel,
                         cudaFuncAttributeMaxDynamicSharedMemorySize, FSMEM);
    flash_kernel<<<dim3(S_LEN / 64, BHN), 128, FSMEM>>>(qp, kp, vp, ap);

    sgemm_nt<<<gg, 256>>>(ap, Wo, bo, out, LAY_PLAIN);
}

// round 2
// speedup vs baseline: 2.2106x; 2.2106x over previous
#include <cuda_runtime.h>
#include <cstdint>

#define D_MODEL 1024
#define S_LEN   2048
#define NB      2
#define NH      16
#define HD      64
#define DQK     128
#define BHN     (NB*NH)

// Scratch (allocation-free rule: __device__ globals)
__device__ float g_Qp[(size_t)BHN * S_LEN * DQK];   // [bh][s][128]: [0:64]=Q/8, [64:128]=lam*tanh(Q)@J
__device__ float g_Kp[(size_t)BHN * S_LEN * DQK];   // [bh][s][128]: [0:64]=K,   [64:128]=tanh(K)
__device__ float g_Vv[(size_t)BHN * S_LEN * HD];    // [bh][s][64]
__device__ float g_attn[(size_t)NB * S_LEN * D_MODEL]; // attention output, (B,S,D)

enum { LAY_PLAIN = 0, LAY_QK = 1, LAY_V = 2 };

__device__ __forceinline__ uint32_t f2tf(float f) {
    uint32_t u;
    asm("cvt.rna.tf32.f32 %0, %1;" : "=r"(u) : "f"(f));
    return u;
}

__device__ __forceinline__ void mma_tf32(float* c, const uint32_t* a, const uint32_t* b) {
    asm volatile(
        "mma.sync.aligned.m16n8k8.row.col.f32.tf32.tf32.f32 "
        "{%0,%1,%2,%3}, {%4,%5,%6,%7}, {%8,%9}, {%0,%1,%2,%3};"
        : "+f"(c[0]), "+f"(c[1]), "+f"(c[2]), "+f"(c[3])
        : "r"(a[0]), "r"(a[1]), "r"(a[2]), "r"(a[3]), "r"(b[0]), "r"(b[1]));
}

// ---------------------------------------------------------------------------
// C[m,n] = sum_k A[m,k]*W[n,k] + bias[n].  M=4096, N=1024, K=1024.
// Block tile 128x64, 128 threads = 4 warps, warp tile 64x32 (4 m-tiles x 4 n-tiles
// of m16n8k8 tf32 mma). Grid (N/64, M/128) = (16, 32).
// ---------------------------------------------------------------------------
__global__ __launch_bounds__(128) void gemm_tf32(
    const float* __restrict__ A, const float* __restrict__ W,
    const float* __restrict__ bias, float* __restrict__ C, int layout)
{
    __shared__ uint32_t As[128 * 36];   // [m][k] k-tile 32, pad 36
    __shared__ uint32_t Ws[64 * 36];    // [n][k]

    const int tid  = threadIdx.x;
    const int lane = tid & 31;
    const int wid  = tid >> 5;
    const int m0   = blockIdx.y * 128;
    const int n0   = blockIdx.x * 64;
    const int wm   = (wid >> 1) * 64;   // warp m offset (0 or 64)
    const int wn   = (wid & 1) * 32;    // warp n offset (0 or 32)

    const int r  = lane >> 2;           // 0..7
    const int q  = lane & 3;            // 0..3

    // global load indexing
    const float* Ap = A + (size_t)(m0 + tid) * D_MODEL;             // 1 row / thread
    const int wrow  = tid >> 1;                                     // 0..63
    const int wkb   = (tid & 1) * 16;                               // 0 or 16
    const float* Wp = W + (size_t)(n0 + wrow) * D_MODEL + wkb;

    float acc[4][4][4];
    #pragma unroll
    for (int i = 0; i < 4; i++)
        #pragma unroll
        for (int j = 0; j < 4; j++)
            #pragma unroll
            for (int e = 0; e < 4; e++) acc[i][j][e] = 0.f;

    for (int k0 = 0; k0 < D_MODEL; k0 += 32) {
        float4 av[8], wv[4];
        #pragma unroll
        for (int j = 0; j < 8; j++)
            av[j] = *reinterpret_cast<const float4*>(Ap + k0 + j * 4);
        #pragma unroll
        for (int j = 0; j < 4; j++)
            wv[j] = *reinterpret_cast<const float4*>(Wp + k0 + j * 4);

        __syncthreads();
        #pragma unroll
        for (int j = 0; j < 8; j++) {
            uint32_t* p = &As[tid * 36 + j * 4];
            p[0] = f2tf(av[j].x); p[1] = f2tf(av[j].y);
            p[2] = f2tf(av[j].z); p[3] = f2tf(av[j].w);
        }
        #pragma unroll
        for (int j = 0; j < 4; j++) {
            uint32_t* p = &Ws[wrow * 36 + wkb + j * 4];
            p[0] = f2tf(wv[j].x); p[1] = f2tf(wv[j].y);
            p[2] = f2tf(wv[j].z); p[3] = f2tf(wv[j].w);
        }
        __syncthreads();

        #pragma unroll
        for (int ks = 0; ks < 4; ks++) {
            const int kb = ks * 8;
            uint32_t af[4][4];
            #pragma unroll
            for (int mt = 0; mt < 4; mt++) {
                const int base = (wm + mt * 16 + r) * 36 + kb + q;
                af[mt][0] = As[base];
                af[mt][1] = As[base + 8 * 36];
                af[mt][2] = As[base + 4];
                af[mt][3] = As[base + 8 * 36 + 4];
            }
            uint32_t bf[4][2];
            #pragma unroll
            for (int nt = 0; nt < 4; nt++) {
                const int base = (wn + nt * 8 + r) * 36 + kb + q;
                bf[nt][0] = Ws[base];
                bf[nt][1] = Ws[base + 4];
            }
            #pragma unroll
            for (int mt = 0; mt < 4; mt++)
                #pragma unroll
                for (int nt = 0; nt < 4; nt++)
                    mma_tf32(acc[mt][nt], af[mt], bf[nt]);
        }
    }

    // epilogue
    #pragma unroll
    for (int mt = 0; mt < 4; mt++) {
        #pragma unroll
        for (int nt = 0; nt < 4; nt++) {
            #pragma unroll
            for (int e = 0; e < 4; e++) {
                const int row = m0 + wm + mt * 16 + r + (e >> 1) * 8;
                const int col = n0 + wn + nt * 8 + q * 2 + (e & 1);
                const float v = acc[mt][nt][e] + __ldg(&bias[col]);
                if (layout == LAY_PLAIN) {
                    C[(size_t)row * D_MODEL + col] = v;
                } else {
                    const int b = row >> 11, s = row & 2047;
                    const int h = col >> 6,  hd = col & 63;
                    if (layout == LAY_QK)
                        C[(((size_t)((b << 4) + h) * S_LEN + s)) * DQK + hd] = v;
                    else
                        C[(((size_t)((b << 4) + h) * S_LEN + s)) * HD + hd] = v;
                }
            }
        }
    }
}

// ---------------------------------------------------------------------------
// Per (bh, 64-row chunk): build extended Q' and K' (fp32).
// ---------------------------------------------------------------------------
__global__ __launch_bounds__(256) void prep_kernel(
    float* __restrict__ Qp, float* __restrict__ Kp,
    const float* __restrict__ J, const float* __restrict__ lam_p)
{
    __shared__ float Js[64 * 65];
    __shared__ float Tq[64 * 65];

    const int bh  = blockIdx.y;
    const int h   = bh & 15;
    const int r0  = blockIdx.x * 64;
    const int tid = threadIdx.x;
    const float lam = lam_p[0];

    float* Qb = Qp + ((size_t)bh * S_LEN + r0) * DQK;
    float* Kb = Kp + ((size_t)bh * S_LEN + r0) * DQK;
    const float* Jh = J + h * (HD * HD);

    for (int i = tid; i < 4096; i += 256)
        Js[(i >> 6) * 65 + (i & 63)] = Jh[i];

    for (int i = tid; i < 4096; i += 256) {
        const int r = i >> 6, d = i & 63;
        const float qv = Qb[r * DQK + d];
        Tq[r * 65 + d] = tanhf(qv);
        Qb[r * DQK + d] = qv * 0.125f;
        const float kv = Kb[r * DQK + d];
        Kb[r * DQK + 64 + d] = tanhf(kv);
    }
    __syncthreads();

    const int e  = tid & 63;
    const int rb = tid >> 6;
    for (int rr = 0; rr < 16; rr++) {
        const int rloc = rb * 16 + rr;
        float acc = 0.f;
        #pragma unroll 8
        for (int d = 0; d < 64; d++)
            acc = fmaf(Tq[rloc * 65 + d], Js[d * 65 + e], acc);
        Qb[rloc * DQK + 64 + e] = lam * acc;
    }
}

// ---------------------------------------------------------------------------
// Causal flash attention with tf32 mma. d_qk=128, d_v=64. BR=BC=64.
// 128 threads = 4 warps; warp w owns rows [w*16, w*16+16) of the 64-row block.
// S tile per warp: 16x64 via 8 n-tiles of m16n8k8 over 16 k-steps.
// PV per warp:     16x64 via 8 n-tiles over 8 k-steps.
// ---------------------------------------------------------------------------
__global__ __launch_bounds__(128) void flash_tf32(
    const float* __restrict__ Qp, const float* __restrict__ Kp,
    const float* __restrict__ V, float* __restrict__ Out)
{
    extern __shared__ uint32_t sm[];
    uint32_t* Qs = sm;                 // [64][132]
    uint32_t* Ks = Qs + 64 * 132;      // [64][132]
    uint32_t* Vs = Ks + 64 * 132;      // [64][72]
    uint32_t* Ps = Vs + 64 * 72;       // [64][68]

    const int bh   = blockIdx.y;
    const int r0   = (gridDim.x - 1 - blockIdx.x) * 64;  // heavy blocks first
    const int tid  = threadIdx.x;
    const int lane = tid & 31;
    const int wid  = tid >> 5;
    const int slab = wid * 16;
    const int r    = lane >> 2;   // 0..7
    const int q    = lane & 3;    // 0..3

    const float* Qb = Qp + (size_t)bh * S_LEN * DQK;
    const float* Kb = Kp + (size_t)bh * S_LEN * DQK;
    const float* Vb = V  + (size_t)bh * S_LEN * HD;

    // load Q tile (64 x 128) -> tf32 smem
    for (int i = tid; i < 2048; i += 128) {            // float4 granules
        const int rr = i >> 5, k4 = (i & 31) * 4;
        float4 v = *reinterpret_cast<const float4*>(Qb + (size_t)(r0 + rr) * DQK + k4);
        uint32_t* p = &Qs[rr * 132 + k4];
        p[0] = f2tf(v.x); p[1] = f2tf(v.y); p[2] = f2tf(v.z); p[3] = f2tf(v.w);
    }

    float m[2] = {-1e30f, -1e30f};
    float l[2] = {0.f, 0.f};
    float O[8][4];
    #pragma unroll
    for (int nt = 0; nt < 8; nt++)
        #pragma unroll
        for (int e = 0; e < 4; e++) O[nt][e] = 0.f;

    const int ntiles = (r0 >> 6) + 1;
    for (int t = 0; t < ntiles; t++) {
        const int c0 = t * 64;
        __syncthreads();
        for (int i = tid; i < 2048; i += 128) {
            const int rr = i >> 5, k4 = (i & 31) * 4;
            float4 v = *reinterpret_cast<const float4*>(Kb + (size_t)(c0 + rr) * DQK + k4);
            uint32_t* p = &Ks[rr * 132 + k4];
            p[0] = f2tf(v.x); p[1] = f2tf(v.y); p[2] = f2tf(v.z); p[3] = f2tf(v.w);
        }
        for (int i = tid; i < 1024; i += 128) {
            const int rr = i >> 4, d4 = (i & 15) * 4;
            float4 v = *reinterpret_cast<const float4*>(Vb + (size_t)(c0 + rr) * HD + d4);
            uint32_t* p = &Vs[rr * 72 + d4];
            p[0] = f2tf(v.x); p[1] = f2tf(v.y); p[2] = f2tf(v.z); p[3] = f2tf(v.w);
        }
        __syncthreads();

        // S = Q' K'^T  (16x64 per warp)
        float s[8][4];
        #pragma unroll
        for (int nt = 0; nt < 8; nt++)
            #pragma unroll
            for (int e = 0; e < 4; e++) s[nt][e] = 0.f;

        #pragma unroll
        for (int ks = 0; ks < 16; ks++) {
            const int kb = ks * 8;
            uint32_t af[4];
            const int abase = (slab + r) * 132 + kb + q;
            af[0] = Qs[abase];
            af[1] = Qs[abase + 8 * 132];
            af[2] = Qs[abase + 4];
            af[3] = Qs[abase + 8 * 132 + 4];
            #pragma unroll
            for (int nt = 0; nt < 8; nt++) {
                const int bbase = (nt * 8 + r) * 132 + kb + q;
                uint32_t bf[2] = { Ks[bbase], Ks[bbase + 4] };
                mma_tf32(s[nt], af, bf);
            }
        }

        // causal mask (only the diagonal tile)
        if (c0 == r0) {
            #pragma unroll
            for (int nt = 0; nt < 8; nt++) {
                #pragma unroll
                for (int e = 0; e < 4; e++) {
                    const int row = slab + r + (e >> 1) * 8;
                    const int col = nt * 8 + q * 2 + (e & 1);
                    if (col > row) s[nt][e] = -1e30f;
                }
            }
        }

        // online softmax per fragment-row (2 rows / thread)
        #pragma unroll
        for (int half = 0; half < 2; half++) {
            float mx = -1e30f;
            #pragma unroll
            for (int nt = 0; nt < 8; nt++)
                mx = fmaxf(mx, fmaxf(s[nt][half * 2], s[nt][half * 2 + 1]));
            mx = fmaxf(mx, __shfl_xor_sync(0xffffffffu, mx, 1));
            mx = fmaxf(mx, __shfl_xor_sync(0xffffffffu, mx, 2));
            const float mn = fmaxf(m[half], mx);
            const float corr = __expf(m[half] - mn);
            m[half] = mn;
            float rs = 0.f;
            #pragma unroll
            for (int nt = 0; nt < 8; nt++) {
                float p0 = __expf(s[nt][half * 2]     - mn);
                float p1 = __expf(s[nt][half * 2 + 1] - mn);
                s[nt][half * 2]     = p0;
                s[nt][half * 2 + 1] = p1;
                rs += p0 + p1;
            }
            rs += __shfl_xor_sync(0xffffffffu, rs, 1);
            rs += __shfl_xor_sync(0xffffffffu, rs, 2);
            l[half] = l[half] * corr + rs;
            #pragma unroll
            for (int nt = 0; nt < 8; nt++) {
                O[nt][half * 2]     *= corr;
                O[nt][half * 2 + 1] *= corr;
            }
        }

        // P -> smem (tf32)
        #pragma unroll
        for (int nt = 0; nt < 8; nt++) {
            #pragma unroll
            for (int e = 0; e < 4; e++) {
                const int row = slab + r + (e >> 1) * 8;
                const int col = nt * 8 + q * 2 + (e & 1);
                Ps[row * 68 + col] = f2tf(s[nt][e]);
            }
        }
        __syncwarp();

        // O += P V   (16x64 per warp, k = 64)
        #pragma unroll
        for (int ks = 0; ks < 8; ks++) {
            const int kb = ks * 8;
            uint32_t af[4];
            const int abase = (slab + r) * 68 + kb + q;
            af[0] = Ps[abase];
            af[1] = Ps[abase + 8 * 68];
            af[2] = Ps[abase + 4];
            af[3] = Ps[abase + 8 * 68 + 4];
            #pragma unroll
            for (int nt = 0; nt < 8; nt++) {
                const int bbase = (kb + q) * 72 + nt * 8 + r;
                uint32_t bf[2] = { Vs[bbase], Vs[bbase + 4 * 72] };
                mma_tf32(O[nt], af, bf);
            }
        }
    }

    // epilogue: normalize and write to g_attn (B,S,D)
    const int b = bh >> 4, h = bh & 15;
    #pragma unroll
    for (int half = 0; half < 2; half++) {
        const float inv = 1.f / l[half];
        const int gr = r0 + slab + r + half * 8;
        #pragma unroll
        for (int nt = 0; nt < 8; nt++) {
            const int d0 = nt * 8 + q * 2;
            float* o = Out + ((size_t)(b * S_LEN + gr)) * D_MODEL + h * HD + d0;
            o[0] = O[nt][half * 2]     * inv;
            o[1] = O[nt][half * 2 + 1] * inv;
        }
    }
}

// ---------------------------------------------------------------------------
extern "C" void kernel_launch(void* const* d_in, const int* in_sizes, int n_in,
                              void* d_out, int out_size)
{
    const float* x   = (const float*)d_in[0];
    const float* Wq  = (const float*)d_in[1];
    const float* bq  = (const float*)d_in[2];
    const float* Wk  = (const float*)d_in[3];
    const float* bk  = (const float*)d_in[4];
    const float* Wv  = (const float*)d_in[5];
    const float* bv  = (const float*)d_in[6];
    const float* Wo  = (const float*)d_in[7];
    const float* bo  = (const float*)d_in[8];
    const float* J   = (const float*)d_in[9];
    const float* lam = (const float*)d_in[10];
    float* out = (float*)d_out;

    float *qp, *kp, *vp, *ap;
    cudaGetSymbolAddress((void**)&qp, g_Qp);
    cudaGetSymbolAddress((void**)&kp, g_Kp);
    cudaGetSymbolAddress((void**)&vp, g_Vv);
    cudaGetSymbolAddress((void**)&ap, g_attn);

    const dim3 gg(D_MODEL / 64, (NB * S_LEN) / 128);   // (16, 32)
    gemm_tf32<<<gg, 128>>>(x, Wq, bq, qp, LAY_QK);
    gemm_tf32<<<gg, 128>>>(x, Wk, bk, kp, LAY_QK);
    gemm_tf32<<<gg, 128>>>(x, Wv, bv, vp, LAY_V);

    prep_kernel<<<dim3(S_LEN / 64, BHN), 256>>>(qp, kp, J, lam);

    const int FSMEM = (64 * 132 * 2 + 64 * 72 + 64 * 68) * (int)sizeof(uint32_t); // 103424
    cudaFuncSetAttribute(flash_tf32,
                         cudaFuncAttributeMaxDynamicSharedMemorySize, FSMEM);
    flash_tf32<<<dim3(S_LEN / 64, BHN), 128, FSMEM>>>(qp, kp, vp, ap);

    gemm_tf32<<<gg, 128>>>(ap, Wo, bo, out, LAY_PLAIN);
}

// round 3
// speedup vs baseline: 2.2452x; 1.0156x over previous
#include <cuda_runtime.h>
#include <cstdint>

#define D_MODEL 1024
#define S_LEN   2048
#define NB      2
#define NH      16
#define HD      64
#define DQK     128
#define BHN     (NB*NH)

// Scratch (allocation-free rule: __device__ globals)
__device__ float g_Qp[(size_t)BHN * S_LEN * DQK];
__device__ float g_Kp[(size_t)BHN * S_LEN * DQK];
__device__ float g_Vv[(size_t)BHN * S_LEN * HD];
__device__ float g_attn[(size_t)NB * S_LEN * D_MODEL];

enum { LAY_PLAIN = 0, LAY_QK = 1, LAY_V = 2 };

__device__ __forceinline__ uint32_t f2tf(float f) {
    uint32_t u;
    asm("cvt.rna.tf32.f32 %0, %1;" : "=r"(u) : "f"(f));
    return u;
}

__device__ __forceinline__ void mma_tf32(float* c, const uint32_t* a, const uint32_t* b) {
    asm volatile(
        "mma.sync.aligned.m16n8k8.row.col.f32.tf32.tf32.f32 "
        "{%0,%1,%2,%3}, {%4,%5,%6,%7}, {%8,%9}, {%0,%1,%2,%3};"
        : "+f"(c[0]), "+f"(c[1]), "+f"(c[2]), "+f"(c[3])
        : "r"(a[0]), "r"(a[1]), "r"(a[2]), "r"(a[3]), "r"(b[0]), "r"(b[1]));
}

// ---------------------------------------------------------------------------
// C[m,n] = sum_k A[m,k]*W[n,k] + bias[n].  M=4096, N=1024, K=1024.
// Block 128x128x16, 256 threads (8 warps, 2x4), warp tile 64x32, double-buffered.
// ---------------------------------------------------------------------------
__global__ __launch_bounds__(256) void gemm_tf32(
    const float* __restrict__ A, const float* __restrict__ W,
    const float* __restrict__ bias, float* __restrict__ C, int layout)
{
    __shared__ uint32_t As[2][128 * 20];
    __shared__ uint32_t Ws[2][128 * 20];

    const int tid  = threadIdx.x;
    const int lane = tid & 31;
    const int wid  = tid >> 5;
    const int m0   = blockIdx.y * 128;
    const int n0   = blockIdx.x * 128;
    const int wm   = (wid & 1) * 64;
    const int wn   = (wid >> 1) * 32;
    const int r    = lane >> 2;
    const int q    = lane & 3;

    const int row  = tid >> 1;
    const int koff = (tid & 1) * 8;
    const float* Ap = A + (size_t)(m0 + row) * D_MODEL + koff;
    const float* Wp = W + (size_t)(n0 + row) * D_MODEL + koff;
    const int sbase = row * 20 + koff;

    // prologue: tile 0 -> buf 0
    {
        float4 a0 = *reinterpret_cast<const float4*>(Ap);
        float4 a1 = *reinterpret_cast<const float4*>(Ap + 4);
        float4 w0 = *reinterpret_cast<const float4*>(Wp);
        float4 w1 = *reinterpret_cast<const float4*>(Wp + 4);
        uint32_t* pa = &As[0][sbase];
        pa[0]=f2tf(a0.x); pa[1]=f2tf(a0.y); pa[2]=f2tf(a0.z); pa[3]=f2tf(a0.w);
        pa[4]=f2tf(a1.x); pa[5]=f2tf(a1.y); pa[6]=f2tf(a1.z); pa[7]=f2tf(a1.w);
        uint32_t* pw = &Ws[0][sbase];
        pw[0]=f2tf(w0.x); pw[1]=f2tf(w0.y); pw[2]=f2tf(w0.z); pw[3]=f2tf(w0.w);
        pw[4]=f2tf(w1.x); pw[5]=f2tf(w1.y); pw[6]=f2tf(w1.z); pw[7]=f2tf(w1.w);
    }
    __syncthreads();

    float acc[4][4][4];
    #pragma unroll
    for (int i = 0; i < 4; i++)
        #pragma unroll
        for (int j = 0; j < 4; j++)
            #pragma unroll
            for (int e = 0; e < 4; e++) acc[i][j][e] = 0.f;

    for (int kt = 0; kt < 64; kt++) {
        const int cur = kt & 1;
        float4 a0, a1, w0, w1;
        if (kt < 63) {
            const int go = (kt + 1) * 16;
            a0 = *reinterpret_cast<const float4*>(Ap + go);
            a1 = *reinterpret_cast<const float4*>(Ap + go + 4);
            w0 = *reinterpret_cast<const float4*>(Wp + go);
            w1 = *reinterpret_cast<const float4*>(Wp + go + 4);
        }

        #pragma unroll
        for (int ks = 0; ks < 2; ks++) {
            const int kb = ks * 8;
            uint32_t af[4][4], bf[4][2];
            #pragma unroll
            for (int mt = 0; mt < 4; mt++) {
                const int base = (wm + mt * 16 + r) * 20 + kb + q;
                af[mt][0] = As[cur][base];
                af[mt][1] = As[cur][base + 8 * 20];
                af[mt][2] = As[cur][base + 4];
                af[mt][3] = As[cur][base + 8 * 20 + 4];
            }
            #pragma unroll
            for (int nt = 0; nt < 4; nt++) {
                const int base = (wn + nt * 8 + r) * 20 + kb + q;
                bf[nt][0] = Ws[cur][base];
                bf[nt][1] = Ws[cur][base + 4];
            }
            #pragma unroll
            for (int mt = 0; mt < 4; mt++)
                #pragma unroll
                for (int nt = 0; nt < 4; nt++)
                    mma_tf32(acc[mt][nt], af[mt], bf[nt]);
        }

        if (kt < 63) {
            uint32_t* pa = &As[cur ^ 1][sbase];
            pa[0]=f2tf(a0.x); pa[1]=f2tf(a0.y); pa[2]=f2tf(a0.z); pa[3]=f2tf(a0.w);
            pa[4]=f2tf(a1.x); pa[5]=f2tf(a1.y); pa[6]=f2tf(a1.z); pa[7]=f2tf(a1.w);
            uint32_t* pw = &Ws[cur ^ 1][sbase];
            pw[0]=f2tf(w0.x); pw[1]=f2tf(w0.y); pw[2]=f2tf(w0.z); pw[3]=f2tf(w0.w);
            pw[4]=f2tf(w1.x); pw[5]=f2tf(w1.y); pw[6]=f2tf(w1.z); pw[7]=f2tf(w1.w);
            __syncthreads();
        }
    }

    #pragma unroll
    for (int mt = 0; mt < 4; mt++) {
        #pragma unroll
        for (int nt = 0; nt < 4; nt++) {
            #pragma unroll
            for (int e = 0; e < 4; e++) {
                const int rw  = m0 + wm + mt * 16 + r + (e >> 1) * 8;
                const int col = n0 + wn + nt * 8 + q * 2 + (e & 1);
                const float v = acc[mt][nt][e] + __ldg(&bias[col]);
                if (layout == LAY_PLAIN) {
                    C[(size_t)rw * D_MODEL + col] = v;
                } else {
                    const int b = rw >> 11, s = rw & 2047;
                    const int h = col >> 6,  hd = col & 63;
                    if (layout == LAY_QK)
                        C[((size_t)((b << 4) + h) * S_LEN + s) * DQK + hd] = v;
                    else
                        C[((size_t)((b << 4) + h) * S_LEN + s) * HD + hd] = v;
                }
            }
        }
    }
}

// ---------------------------------------------------------------------------
// Per (bh, 64-row chunk): build extended Q' and K' (fp32).
// ---------------------------------------------------------------------------
__global__ __launch_bounds__(256) void prep_kernel(
    float* __restrict__ Qp, float* __restrict__ Kp,
    const float* __restrict__ J, const float* __restrict__ lam_p)
{
    __shared__ float Js[64 * 68];
    __shared__ float Tq[64 * 68];

    const int bh  = blockIdx.y;
    const int h   = bh & 15;
    const int r0  = blockIdx.x * 64;
    const int tid = threadIdx.x;
    const float lam = lam_p[0];

    float* Qb = Qp + ((size_t)bh * S_LEN + r0) * DQK;
    float* Kb = Kp + ((size_t)bh * S_LEN + r0) * DQK;
    const float* Jh = J + h * (HD * HD);

    for (int i = tid; i < 4096; i += 256)
        Js[(i >> 6) * 68 + (i & 63)] = Jh[i];

    for (int i = tid; i < 4096; i += 256) {
        const int r = i >> 6, d = i & 63;
        const float qv = Qb[r * DQK + d];
        Tq[r * 68 + d] = tanhf(qv);
        Qb[r * DQK + d] = qv * 0.125f;
        const float kv = Kb[r * DQK + d];
        Kb[r * DQK + 64 + d] = tanhf(kv);
    }
    __syncthreads();

    const int e4 = (tid & 15) * 4;
    const int rg = tid >> 4;          // 0..15 -> 4 rows each
    #pragma unroll
    for (int rr = 0; rr < 4; rr++) {
        const int rloc = rg * 4 + rr;
        float ax = 0.f, ay = 0.f, az = 0.f, aw = 0.f;
        #pragma unroll 8
        for (int d = 0; d < 64; d++) {
            const float t = Tq[rloc * 68 + d];
            const float4 jv = *reinterpret_cast<const float4*>(&Js[d * 68 + e4]);
            ax = fmaf(t, jv.x, ax); ay = fmaf(t, jv.y, ay);
            az = fmaf(t, jv.z, az); aw = fmaf(t, jv.w, aw);
        }
        float4 o = make_float4(lam * ax, lam * ay, lam * az, lam * aw);
        *reinterpret_cast<float4*>(&Qb[rloc * DQK + 64 + e4]) = o;
    }
}

// ---------------------------------------------------------------------------
// Causal flash attention, tf32 mma, fragment-layout smem.
// BR=BC=64, 128 threads = 4 warps (16 rows each).
// Qs: A-frag layout, frag_row = w*16+ks, stride 132 (v4 reads).
// Ks: B-frag layout, frag_row = nt*16+ks, stride 66 (v2 reads, cf stores).
// Vs: B-frag layout, frag_row = nt*8+ks,  stride 66.
// Ps: C-layout [64][68] (same as validated R1 path).
// ---------------------------------------------------------------------------
__global__ __launch_bounds__(128) void flash_tf32(
    const float* __restrict__ Qp, const float* __restrict__ Kp,
    const float* __restrict__ V, float* __restrict__ Out)
{
    extern __shared__ uint32_t sm[];
    uint32_t* Qs = sm;                     // 64*132 = 8448
    uint32_t* Ks = Qs + 64 * 132;          // 128*66 = 8448
    uint32_t* Vs = Ks + 128 * 66;          // 64*66  = 4224
    uint32_t* Ps = Vs + 64 * 66;           // 64*68  = 4352

    const int bh   = blockIdx.y;
    const int r0   = (gridDim.x - 1 - blockIdx.x) * 64;
    const int tid  = threadIdx.x;
    const int lane = tid & 31;
    const int wid  = tid >> 5;
    const int slab = wid * 16;
    const int r    = lane >> 2;
    const int q    = lane & 3;

    const float* Qb = Qp + (size_t)bh * S_LEN * DQK;
    const float* Kb = Kp + (size_t)bh * S_LEN * DQK;
    const float* Vb = V  + (size_t)bh * S_LEN * HD;

    // Q tile -> A-frag layout
    for (int i = tid; i < 2048; i += 128) {
        const int rr = i >> 5, k4 = i & 31;
        float4 v = *reinterpret_cast<const float4*>(Qb + (size_t)(r0 + rr) * DQK + k4 * 4);
        const int w = rr >> 4, fr = rr & 7, hh = (rr >> 3) & 1;
        const int ks = k4 >> 1, w2 = k4 & 1;
        const int word = hh + 2 * w2;
        uint32_t* base = &Qs[(w * 16 + ks) * 132 + word];
        base[(fr * 4 + 0) * 4] = f2tf(v.x);
        base[(fr * 4 + 1) * 4] = f2tf(v.y);
        base[(fr * 4 + 2) * 4] = f2tf(v.z);
        base[(fr * 4 + 3) * 4] = f2tf(v.w);
    }

    float m[2] = {-1e30f, -1e30f};
    float l[2] = {0.f, 0.f};
    float O[8][4];
    #pragma unroll
    for (int nt = 0; nt < 8; nt++)
        #pragma unroll
        for (int e = 0; e < 4; e++) O[nt][e] = 0.f;

    const int ntiles = (r0 >> 6) + 1;
    for (int t = 0; t < ntiles; t++) {
        const int c0 = t * 64;
        __syncthreads();
        // K' tile -> B-frag layout
        for (int i = tid; i < 2048; i += 128) {
            const int n = i >> 5, k4 = i & 31;
            float4 v = *reinterpret_cast<const float4*>(Kb + (size_t)(c0 + n) * DQK + k4 * 4);
            const int nt = n >> 3, fr = n & 7;
            const int ks = k4 >> 1, word = k4 & 1;
            uint32_t* base = &Ks[(nt * 16 + ks) * 66 + word];
            base[(fr * 4 + 0) * 2] = f2tf(v.x);
            base[(fr * 4 + 1) * 2] = f2tf(v.y);
            base[(fr * 4 + 2) * 2] = f2tf(v.z);
            base[(fr * 4 + 3) * 2] = f2tf(v.w);
        }
        // V tile -> B-frag layout
        for (int i = tid; i < 1024; i += 128) {
            const int j = i >> 4, d4 = i & 15;
            float4 v = *reinterpret_cast<const float4*>(Vb + (size_t)(c0 + j) * HD + d4 * 4);
            const int ks = j >> 3, qq = j & 3, word = (j >> 2) & 1;
            const int d0 = d4 * 4;
            const float vv[4] = {v.x, v.y, v.z, v.w};
            #pragma unroll
            for (int c = 0; c < 4; c++) {
                const int d = d0 + c, nt = d >> 3, fr = d & 7;
                Vs[(nt * 8 + ks) * 66 + (fr * 4 + qq) * 2 + word] = f2tf(vv[c]);
            }
        }
        __syncthreads();

        // S = Q' K'^T
        float s[8][4];
        #pragma unroll
        for (int nt = 0; nt < 8; nt++)
            #pragma unroll
            for (int e = 0; e < 4; e++) s[nt][e] = 0.f;

        #pragma unroll
        for (int ks = 0; ks < 16; ks++) {
            uint4 av = *reinterpret_cast<const uint4*>(&Qs[(wid * 16 + ks) * 132 + lane * 4]);
            const uint32_t af[4] = {av.x, av.y, av.z, av.w};
            #pragma unroll
            for (int nt = 0; nt < 8; nt++) {
                uint2 bv = *reinterpret_cast<const uint2*>(&Ks[(nt * 16 + ks) * 66 + lane * 2]);
                const uint32_t bf[2] = {bv.x, bv.y};
                mma_tf32(s[nt], af, bf);
            }
        }

        if (c0 == r0) {
            #pragma unroll
            for (int nt = 0; nt < 8; nt++)
                #pragma unroll
                for (int e = 0; e < 4; e++) {
                    const int rw  = slab + r + (e >> 1) * 8;
                    const int col = nt * 8 + q * 2 + (e & 1);
                    if (col > rw) s[nt][e] = -1e30f;
                }
        }

        #pragma unroll
        for (int half = 0; half < 2; half++) {
            float mx = -1e30f;
            #pragma unroll
            for (int nt = 0; nt < 8; nt++)
                mx = fmaxf(mx, fmaxf(s[nt][half * 2], s[nt][half * 2 + 1]));
            mx = fmaxf(mx, __shfl_xor_sync(0xffffffffu, mx, 1));
            mx = fmaxf(mx, __shfl_xor_sync(0xffffffffu, mx, 2));
            const float mn = fmaxf(m[half], mx);
            const float corr = __expf(m[half] - mn);
            m[half] = mn;
            float rs = 0.f;
            #pragma unroll
            for (int nt = 0; nt < 8; nt++) {
                const float p0 = __expf(s[nt][half * 2]     - mn);
                const float p1 = __expf(s[nt][half * 2 + 1] - mn);
                s[nt][half * 2]     = p0;
                s[nt][half * 2 + 1] = p1;
                rs += p0 + p1;
            }
            rs += __shfl_xor_sync(0xffffffffu, rs, 1);
            rs += __shfl_xor_sync(0xffffffffu, rs, 2);
            l[half] = l[half] * corr + rs;
            #pragma unroll
            for (int nt = 0; nt < 8; nt++) {
                O[nt][half * 2]     *= corr;
                O[nt][half * 2 + 1] *= corr;
            }
        }

        // P -> smem (C-layout)
        #pragma unroll
        for (int nt = 0; nt < 8; nt++)
            #pragma unroll
            for (int e = 0; e < 4; e++) {
                const int rw  = slab + r + (e >> 1) * 8;
                const int col = nt * 8 + q * 2 + (e & 1);
                Ps[rw * 68 + col] = f2tf(s[nt][e]);
            }
        __syncwarp();

        // O += P V
        #pragma unroll
        for (int ks = 0; ks < 8; ks++) {
            const int kb = ks * 8;
            const int abase = (slab + r) * 68 + kb + q;
            uint32_t af[4];
            af[0] = Ps[abase];
            af[1] = Ps[abase + 8 * 68];
            af[2] = Ps[abase + 4];
            af[3] = Ps[abase + 8 * 68 + 4];
            #pragma unroll
            for (int nt = 0; nt < 8; nt++) {
                uint2 bv = *reinterpret_cast<const uint2*>(&Vs[(nt * 8 + ks) * 66 + lane * 2]);
                const uint32_t bf[2] = {bv.x, bv.y};
                mma_tf32(O[nt], af, bf);
            }
        }
    }

    const int b = bh >> 4, h = bh & 15;
    #pragma unroll
    for (int half = 0; half < 2; half++) {
        const float inv = 1.f / l[half];
        const int gr = r0 + slab + r + half * 8;
        #pragma unroll
        for (int nt = 0; nt < 8; nt++) {
            const int d0 = nt * 8 + q * 2;
            float* o = Out + ((size_t)(b * S_LEN + gr)) * D_MODEL + h * HD + d0;
            o[0] = O[nt][half * 2]     * inv;
            o[1] = O[nt][half * 2 + 1] * inv;
        }
    }
}

// ---------------------------------------------------------------------------
extern "C" void kernel_launch(void* const* d_in, const int* in_sizes, int n_in,
                              void* d_out, int out_size)
{
    const float* x   = (const float*)d_in[0];
    const float* Wq  = (const float*)d_in[1];
    const float* bq  = (const float*)d_in[2];
    const float* Wk  = (const float*)d_in[3];
    const float* bk  = (const float*)d_in[4];
    const float* Wv  = (const float*)d_in[5];
    const float* bv  = (const float*)d_in[6];
    const float* Wo  = (const float*)d_in[7];
    const float* bo  = (const float*)d_in[8];
    const float* J   = (const float*)d_in[9];
    const float* lam = (const float*)d_in[10];
    float* out = (float*)d_out;

    float *qp, *kp, *vp, *ap;
    cudaGetSymbolAddress((void**)&qp, g_Qp);
    cudaGetSymbolAddress((void**)&kp, g_Kp);
    cudaGetSymbolAddress((void**)&vp, g_Vv);
    cudaGetSymbolAddress((void**)&ap, g_attn);

    const dim3 gg(D_MODEL / 128, (NB * S_LEN) / 128);   // (8, 32)
    gemm_tf32<<<gg, 256>>>(x, Wq, bq, qp, LAY_QK);
    gemm_tf32<<<gg, 256>>>(x, Wk, bk, kp, LAY_QK);
    gemm_tf32<<<gg, 256>>>(x, Wv, bv, vp, LAY_V);

    prep_kernel<<<dim3(S_LEN / 64, BHN), 256>>>(qp, kp, J, lam);

    const int FSMEM = (64 * 132 + 128 * 66 + 64 * 66 + 64 * 68) * (int)sizeof(uint32_t); // 101888
    cudaFuncSetAttribute(flash_tf32,
                         cudaFuncAttributeMaxDynamicSharedMemorySize, FSMEM);
    flash_tf32<<<dim3(S_LEN / 64, BHN), 128, FSMEM>>>(qp, kp, vp, ap);

    gemm_tf32<<<gg, 256>>>(ap, Wo, bo, out, LAY_PLAIN);
}

// round 5
// speedup vs baseline: 2.7534x; 1.2264x over previous
#include <cuda_runtime.h>
#include <cuda_fp16.h>
#include <cstdint>

#define D_MODEL 1024
#define S_LEN   2048
#define NB      2
#define NH      16
#define HD      64
#define DQK     128
#define BHN     (NB*NH)

// Scratch (allocation-free rule: __device__ globals)
__device__ __half g_Qh[(size_t)BHN * S_LEN * DQK];  // [bh][s][128]: [0:64]=Q/8, [64:128]=lam*tanh(Q)@J
__device__ __half g_Kh[(size_t)BHN * S_LEN * DQK];  // [bh][s][128]: [0:64]=K,   [64:128]=tanh(K)
__device__ __half g_Vh[(size_t)BHN * S_LEN * HD];   // [bh][s][64]
__device__ float  g_attn[(size_t)NB * S_LEN * D_MODEL];

enum { LAY_PLAIN = 0, LAY_Q = 1, LAY_K = 2, LAY_V = 3 };

__device__ __forceinline__ void mma_f16(float* c, const uint32_t* a, const uint32_t* b) {
    asm volatile(
        "mma.sync.aligned.m16n8k16.row.col.f32.f16.f16.f32 "
        "{%0,%1,%2,%3}, {%4,%5,%6,%7}, {%8,%9}, {%0,%1,%2,%3};"
        : "+f"(c[0]), "+f"(c[1]), "+f"(c[2]), "+f"(c[3])
        : "r"(a[0]), "r"(a[1]), "r"(a[2]), "r"(a[3]), "r"(b[0]), "r"(b[1]));
}

__device__ __forceinline__ uint32_t packh2(float x, float y) {
    __half2 h = __floats2half2_rn(x, y);
    return *reinterpret_cast<uint32_t*>(&h);
}

// ---------------------------------------------------------------------------
// C[m,n] = sum_k A[m,k]*W[n,k] + bias[n].  M=4096, N=1024, K=1024.
// fp16 mma m16n8k16, block 128x128x32, 256 threads (8 warps), warp 64x32,
// double-buffered smem (fp16, stride 40 halves).
// ---------------------------------------------------------------------------
__global__ __launch_bounds__(256) void gemm_f16(
    const float* __restrict__ A, const float* __restrict__ W,
    const float* __restrict__ bias,
    float* __restrict__ Cf, __half* __restrict__ Ch, int layout)
{
    __shared__ __align__(16) __half As[2][128 * 40];
    __shared__ __align__(16) __half Ws[2][128 * 40];

    const int tid  = threadIdx.x;
    const int lane = tid & 31;
    const int wid  = tid >> 5;
    const int m0   = blockIdx.y * 128;
    const int n0   = blockIdx.x * 128;
    const int wm   = (wid & 1) * 64;
    const int wn   = (wid >> 1) * 32;
    const int r    = lane >> 2;
    const int q    = lane & 3;

    const int row   = tid >> 1;
    const int koff  = (tid & 1) * 16;
    const float* Ap = A + (size_t)(m0 + row) * D_MODEL + koff;
    const float* Wp = W + (size_t)(n0 + row) * D_MODEL + koff;
    const int sb    = row * 40 + koff;   // halves

    // prologue: k-tile 0 -> buf 0
    {
        #pragma unroll
        for (int c = 0; c < 4; c++) {
            float4 a = *reinterpret_cast<const float4*>(Ap + c * 4);
            float4 w = *reinterpret_cast<const float4*>(Wp + c * 4);
            __half2* pa = reinterpret_cast<__half2*>(&As[0][sb + c * 4]);
            pa[0] = __floats2half2_rn(a.x, a.y);
            pa[1] = __floats2half2_rn(a.z, a.w);
            __half2* pw = reinterpret_cast<__half2*>(&Ws[0][sb + c * 4]);
            pw[0] = __floats2half2_rn(w.x, w.y);
            pw[1] = __floats2half2_rn(w.z, w.w);
        }
    }
    __syncthreads();

    float acc[4][4][4];
    #pragma unroll
    for (int i = 0; i < 4; i++)
        #pragma unroll
        for (int j = 0; j < 4; j++)
            #pragma unroll
            for (int e = 0; e < 4; e++) acc[i][j][e] = 0.f;

    for (int kt = 0; kt < 32; kt++) {
        const int cur = kt & 1;
        float4 av[4], wv[4];
        if (kt < 31) {
            const int go = (kt + 1) * 32;
            #pragma unroll
            for (int c = 0; c < 4; c++) {
                av[c] = *reinterpret_cast<const float4*>(Ap + go + c * 4);
                wv[c] = *reinterpret_cast<const float4*>(Wp + go + c * 4);
            }
        }

        #pragma unroll
        for (int ks = 0; ks < 2; ks++) {
            const int kb = ks * 16;
            uint32_t af[4][4], bf[4][2];
            #pragma unroll
            for (int mt = 0; mt < 4; mt++) {
                const __half* p = &As[cur][(wm + mt * 16 + r) * 40 + kb + 2 * q];
                af[mt][0] = *reinterpret_cast<const uint32_t*>(p);
                af[mt][1] = *reinterpret_cast<const uint32_t*>(p + 8 * 40);
                af[mt][2] = *reinterpret_cast<const uint32_t*>(p + 8);
                af[mt][3] = *reinterpret_cast<const uint32_t*>(p + 8 * 40 + 8);
            }
            #pragma unroll
            for (int nt = 0; nt < 4; nt++) {
                const __half* p = &Ws[cur][(wn + nt * 8 + r) * 40 + kb + 2 * q];
                bf[nt][0] = *reinterpret_cast<const uint32_t*>(p);
                bf[nt][1] = *reinterpret_cast<const uint32_t*>(p + 8);
            }
            #pragma unroll
            for (int mt = 0; mt < 4; mt++)
                #pragma unroll
                for (int nt = 0; nt < 4; nt++)
                    mma_f16(acc[mt][nt], af[mt], bf[nt]);
        }

        if (kt < 31) {
            const int nxt = cur ^ 1;
            #pragma unroll
            for (int c = 0; c < 4; c++) {
                __half2* pa = reinterpret_cast<__half2*>(&As[nxt][sb + c * 4]);
                pa[0] = __floats2half2_rn(av[c].x, av[c].y);
                pa[1] = __floats2half2_rn(av[c].z, av[c].w);
                __half2* pw = reinterpret_cast<__half2*>(&Ws[nxt][sb + c * 4]);
                pw[0] = __floats2half2_rn(wv[c].x, wv[c].y);
                pw[1] = __floats2half2_rn(wv[c].z, wv[c].w);
            }
            __syncthreads();
        }
    }

    // epilogue: pairs (cols c, c+1) at rows rw and rw+8
    #pragma unroll
    for (int mt = 0; mt < 4; mt++) {
        #pragma unroll
        for (int nt = 0; nt < 4; nt++) {
            const int rw0 = m0 + wm + mt * 16 + r;
            const int c0c = n0 + wn + nt * 8 + 2 * q;
            const float2 bb = *reinterpret_cast<const float2*>(&bias[c0c]);
            #pragma unroll
            for (int hh = 0; hh < 2; hh++) {
                const int rw = rw0 + hh * 8;
                const float v0 = acc[mt][nt][hh * 2]     + bb.x;
                const float v1 = acc[mt][nt][hh * 2 + 1] + bb.y;
                if (layout == LAY_PLAIN) {
                    *reinterpret_cast<float2*>(&Cf[(size_t)rw * D_MODEL + c0c]) =
                        make_float2(v0, v1);
                } else {
                    const int b = rw >> 11, s = rw & 2047;
                    const int h = c0c >> 6, hd = c0c & 63;
                    const size_t base = ((size_t)((b << 4) + h) * S_LEN + s);
                    if (layout == LAY_Q) {
                        *reinterpret_cast<__half2*>(&Ch[base * DQK + hd]) =
                            __floats2half2_rn(v0 * 0.125f, v1 * 0.125f);
                    } else if (layout == LAY_K) {
                        *reinterpret_cast<__half2*>(&Ch[base * DQK + hd]) =
                            __floats2half2_rn(v0, v1);
                        *reinterpret_cast<__half2*>(&Ch[base * DQK + 64 + hd]) =
                            __floats2half2_rn(tanhf(v0), tanhf(v1));
                    } else { // LAY_V
                        *reinterpret_cast<__half2*>(&Ch[base * HD + hd]) =
                            __floats2half2_rn(v0, v1);
                    }
                }
            }
        }
    }
}

// ---------------------------------------------------------------------------
// prep: Q'[r,64:128] = lam * tanh(Q[r,:]) @ J_h   (Q stored scaled by 1/8)
// ---------------------------------------------------------------------------
__global__ __launch_bounds__(256) void prep_kernel(
    __half* __restrict__ Qh, const float* __restrict__ J,
    const float* __restrict__ lam_p)
{
    __shared__ float Js[64 * 68];
    __shared__ float Tq[64 * 68];

    const int bh  = blockIdx.y;
    const int h   = bh & 15;
    const int r0  = blockIdx.x * 64;
    const int tid = threadIdx.x;
    const float lam = lam_p[0];

    __half* Qb = Qh + ((size_t)bh * S_LEN + r0) * DQK;
    const float* Jh = J + h * (HD * HD);

    for (int i = tid; i < 4096; i += 256)
        Js[(i >> 6) * 68 + (i & 63)] = Jh[i];

    for (int i = tid; i < 4096; i += 256) {
        const int r = i >> 6, d = i & 63;
        const float qs = __half2float(Qb[r * DQK + d]);   // scaled by 1/8
        Tq[r * 68 + d] = tanhf(qs * 8.0f);
    }
    __syncthreads();

    const int e4 = (tid & 15) * 4;
    const int rg = tid >> 4;
    #pragma unroll
    for (int rr = 0; rr < 4; rr++) {
        const int rl = rg * 4 + rr;
        float ax = 0.f, ay = 0.f, az = 0.f, aw = 0.f;
        #pragma unroll 8
        for (int d = 0; d < 64; d++) {
            const float t = Tq[rl * 68 + d];
            const float4 jv = *reinterpret_cast<const float4*>(&Js[d * 68 + e4]);
            ax = fmaf(t, jv.x, ax); ay = fmaf(t, jv.y, ay);
            az = fmaf(t, jv.z, az); aw = fmaf(t, jv.w, aw);
        }
        __half2* o = reinterpret_cast<__half2*>(&Qb[rl * DQK + 64 + e4]);
        o[0] = __floats2half2_rn(lam * ax, lam * ay);
        o[1] = __floats2half2_rn(lam * az, lam * aw);
    }
}

// ---------------------------------------------------------------------------
// Causal flash attention, fp16 mma. BR=128, BC=64, 256 threads (8 warps,
// 16 rows each). Q fragments in registers; P reused from C-frags as A-frags.
// Ks row-major fp16 [64][136]; Vs transposed [64 d][72 j].
// ---------------------------------------------------------------------------
__global__ __launch_bounds__(256) void flash_f16(
    const __half* __restrict__ Qh, const __half* __restrict__ Kh,
    const __half* __restrict__ Vh, float* __restrict__ Out)
{
    __shared__ __align__(16) __half Ks[64 * 136];
    __shared__ __align__(16) __half Vs[64 * 72];     // [d][j]

    const int bh   = blockIdx.y;
    const int r0   = (int)(gridDim.x - 1 - blockIdx.x) * 128;  // heavy first
    const int tid  = threadIdx.x;
    const int lane = tid & 31;
    const int wid  = tid >> 5;
    const int slab = wid * 16;
    const int r    = lane >> 2;
    const int q    = lane & 3;

    const __half* Qb = Qh + (size_t)bh * S_LEN * DQK;
    const __half* Kb = Kh + (size_t)bh * S_LEN * DQK;
    const __half* Vb = Vh + (size_t)bh * S_LEN * HD;

    // Q fragments -> registers (16 rows x 128 k per warp, 8 k-steps)
    uint32_t qf[8][4];
    {
        const uint32_t* Qw = reinterpret_cast<const uint32_t*>(Qb);
        const int rowA = (r0 + slab + r) * 64;       // words per row = 64
        #pragma unroll
        for (int ks = 0; ks < 8; ks++) {
            const int c = ks * 8 + q;
            qf[ks][0] = Qw[rowA + c];
            qf[ks][1] = Qw[rowA + 512 + c];          // +8 rows
            qf[ks][2] = Qw[rowA + c + 4];
            qf[ks][3] = Qw[rowA + 512 + c + 4];
        }
    }

    float m[2] = {-1e30f, -1e30f};
    float l[2] = {0.f, 0.f};
    float O[8][4];
    #pragma unroll
    for (int nt = 0; nt < 8; nt++)
        #pragma unroll
        for (int e = 0; e < 4; e++) O[nt][e] = 0.f;

    const int ntiles = (r0 >> 6) + 2;
    for (int t = 0; t < ntiles; t++) {
        const int c0 = t * 64;
        __syncthreads();
        // K' tile: 64 rows x 128 halves, row-major
        {
            const uint4* src = reinterpret_cast<const uint4*>(Kb + (size_t)c0 * DQK);
            for (int i = tid; i < 1024; i += 256) {
                const int rr = i >> 4, g = i & 15;
                *reinterpret_cast<uint4*>(&Ks[rr * 136 + g * 8]) = src[rr * 16 + g];
            }
        }
        // V tile: 64 x 64, store transposed [d][j]
        {
            const uint2* src = reinterpret_cast<const uint2*>(Vb + (size_t)c0 * HD);
            for (int i = tid; i < 1024; i += 256) {
                const int rr = i >> 4, g = i & 15;
                uint2 v = src[rr * 16 + g];
                const __half* hp = reinterpret_cast<const __half*>(&v);
                const int d0 = g * 4;
                #pragma unroll
                for (int c = 0; c < 4; c++)
                    Vs[(d0 + c) * 72 + rr] = hp[c];
            }
        }
        __syncthreads();

        const bool active = (c0 <= r0 + slab + 15);
        if (active) {
            // S = Q' K'^T  (16 x 64 per warp)
            float s[8][4];
            #pragma unroll
            for (int nt = 0; nt < 8; nt++)
                #pragma unroll
                for (int e = 0; e < 4; e++) s[nt][e] = 0.f;

            #pragma unroll
            for (int ks = 0; ks < 8; ks++) {
                #pragma unroll
                for (int nt = 0; nt < 8; nt++) {
                    const __half* p = &Ks[(nt * 8 + r) * 136 + ks * 16 + 2 * q];
                    uint32_t bf[2];
                    bf[0] = *reinterpret_cast<const uint32_t*>(p);
                    bf[1] = *reinterpret_cast<const uint32_t*>(p + 8);
                    mma_f16(s[nt], qf[ks], bf);
                }
            }

            // causal mask (partial tiles only)
            if (c0 + 63 > r0 + slab) {
                #pragma unroll
                for (int nt = 0; nt < 8; nt++)
                    #pragma unroll
                    for (int e = 0; e < 4; e++) {
                        const int gr = r0 + slab + r + (e >> 1) * 8;
                        const int gc = c0 + nt * 8 + 2 * q + (e & 1);
                        if (gc > gr) s[nt][e] = -1e30f;
                    }
            }

            // online softmax (2 rows / thread)
            #pragma unroll
            for (int half = 0; half < 2; half++) {
                float mx = -1e30f;
                #pragma unroll
                for (int nt = 0; nt < 8; nt++)
                    mx = fmaxf(mx, fmaxf(s[nt][half * 2], s[nt][half * 2 + 1]));
                mx = fmaxf(mx, __shfl_xor_sync(0xffffffffu, mx, 1));
                mx = fmaxf(mx, __shfl_xor_sync(0xffffffffu, mx, 2));
                const float mn = fmaxf(m[half], mx);
                const float corr = __expf(m[half] - mn);
                m[half] = mn;
                float rs = 0.f;
                #pragma unroll
                for (int nt = 0; nt < 8; nt++) {
                    const float p0 = __expf(s[nt][half * 2]     - mn);
                    const float p1 = __expf(s[nt][half * 2 + 1] - mn);
                    s[nt][half * 2]     = p0;
                    s[nt][half * 2 + 1] = p1;
                    rs += p0 + p1;
                }
                rs += __shfl_xor_sync(0xffffffffu, rs, 1);
                rs += __shfl_xor_sync(0xffffffffu, rs, 2);
                l[half] = l[half] * corr + rs;
                #pragma unroll
                for (int nt = 0; nt < 8; nt++) {
                    O[nt][half * 2]     *= corr;
                    O[nt][half * 2 + 1] *= corr;
                }
            }

            // O += P V : P from C-frags as A-frags (fp16), V from Vs[d][j]
            #pragma unroll
            for (int j = 0; j < 4; j++) {          // k-steps of 16 over BC=64
                uint32_t ap[4];
                ap[0] = packh2(s[2*j][0],   s[2*j][1]);
                ap[1] = packh2(s[2*j][2],   s[2*j][3]);
                ap[2] = packh2(s[2*j+1][0], s[2*j+1][1]);
                ap[3] = packh2(s[2*j+1][2], s[2*j+1][3]);
                #pragma unroll
                for (int nt = 0; nt < 8; nt++) {
                    const __half* p = &Vs[(nt * 8 + r) * 72 + j * 16 + 2 * q];
                    uint32_t bf[2];
                    bf[0] = *reinterpret_cast<const uint32_t*>(p);
                    bf[1] = *reinterpret_cast<const uint32_t*>(p + 8);
                    mma_f16(O[nt], ap, bf);
                }
            }
        }
    }

    // epilogue
    const int b = bh >> 4, h = bh & 15;
    #pragma unroll
    for (int half = 0; half < 2; half++) {
        const float inv = 1.f / l[half];
        const int gr = r0 + slab + r + half * 8;
        #pragma unroll
        for (int nt = 0; nt < 8; nt++) {
            const int d0 = nt * 8 + 2 * q;
            *reinterpret_cast<float2*>(
                Out + ((size_t)(b * S_LEN + gr)) * D_MODEL + h * HD + d0) =
                make_float2(O[nt][half * 2] * inv, O[nt][half * 2 + 1] * inv);
        }
    }
}

// ---------------------------------------------------------------------------
extern "C" void kernel_launch(void* const* d_in, const int* in_sizes, int n_in,
                              void* d_out, int out_size)
{
    const float* x   = (const float*)d_in[0];
    const float* Wq  = (const float*)d_in[1];
    const float* bq  = (const float*)d_in[2];
    const float* Wk  = (const float*)d_in[3];
    const float* bk  = (const float*)d_in[4];
    const float* Wv  = (const float*)d_in[5];
    const float* bv  = (const float*)d_in[6];
    const float* Wo  = (const float*)d_in[7];
    const float* bo  = (const float*)d_in[8];
    const float* J   = (const float*)d_in[9];
    const float* lam = (const float*)d_in[10];
    float* out = (float*)d_out;

    __half *qh, *kh, *vh;
    float  *ap;
    cudaGetSymbolAddress((void**)&qh, g_Qh);
    cudaGetSymbolAddress((void**)&kh, g_Kh);
    cudaGetSymbolAddress((void**)&vh, g_Vh);
    cudaGetSymbolAddress((void**)&ap, g_attn);

    const dim3 gg(D_MODEL / 128, (NB * S_LEN) / 128);   // (8, 32)
    gemm_f16<<<gg, 256>>>(x, Wq, bq, nullptr, qh, LAY_Q);
    gemm_f16<<<gg, 256>>>(x, Wk, bk, nullptr, kh, LAY_K);
    gemm_f16<<<gg, 256>>>(x, Wv, bv, nullptr, vh, LAY_V);

    prep_kernel<<<dim3(S_LEN / 64, BHN), 256>>>(qh, J, lam);

    flash_f16<<<dim3(S_LEN / 128, BHN), 256>>>(qh, kh, vh, ap);

    gemm_f16<<<gg, 256>>>(ap, Wo, bo, out, nullptr, LAY_PLAIN);
}

// round 6
// speedup vs baseline: 5.1156x; 1.8579x over previous
#include <cuda_runtime.h>
#include <cuda_fp16.h>
#include <cstdint>

#define D_MODEL 1024
#define S_LEN   2048
#define NB      2
#define NH      16
#define HD      64
#define DQK     128
#define BHN     (NB*NH)

// Scratch (allocation-free rule: __device__ globals)
__device__ __half g_xh [(size_t)NB * S_LEN * D_MODEL];
__device__ __half g_Wqh[D_MODEL * D_MODEL];
__device__ __half g_Wkh[D_MODEL * D_MODEL];
__device__ __half g_Wvh[D_MODEL * D_MODEL];
__device__ __half g_Woh[D_MODEL * D_MODEL];
__device__ __half g_Jth[NH * HD * HD];              // [h][e][d] = lam * J[h][d][e]
__device__ __half g_Qh[(size_t)BHN * S_LEN * DQK];  // [0:64]=Q/8, [64:128]=lam*tanh(Q)@J
__device__ __half g_Kh[(size_t)BHN * S_LEN * DQK];  // [0:64]=K,   [64:128]=tanh(K)
__device__ __half g_Vh[(size_t)BHN * S_LEN * HD];
__device__ __half g_attnh[(size_t)NB * S_LEN * D_MODEL];

__device__ __forceinline__ void mma_f16(float* c, const uint32_t* a, const uint32_t* b) {
    asm volatile(
        "mma.sync.aligned.m16n8k16.row.col.f32.f16.f16.f32 "
        "{%0,%1,%2,%3}, {%4,%5,%6,%7}, {%8,%9}, {%0,%1,%2,%3};"
        : "+f"(c[0]), "+f"(c[1]), "+f"(c[2]), "+f"(c[3])
        : "r"(a[0]), "r"(a[1]), "r"(a[2]), "r"(a[3]), "r"(b[0]), "r"(b[1]));
}

__device__ __forceinline__ uint32_t packh2(float x, float y) {
    __half2 h = __floats2half2_rn(x, y);
    return *reinterpret_cast<uint32_t*>(&h);
}

__device__ __forceinline__ uint32_t smaddr(const void* p) {
    uint32_t a;
    asm("{ .reg .u64 t; cvta.to.shared.u64 t, %1; cvt.u32.u64 %0, t; }"
        : "=r"(a) : "l"(p));
    return a;
}

__device__ __forceinline__ void ldsm_x4(uint32_t& r0, uint32_t& r1, uint32_t& r2,
                                        uint32_t& r3, uint32_t addr) {
    asm volatile("ldmatrix.sync.aligned.m8n8.x4.shared.b16 {%0,%1,%2,%3}, [%4];"
                 : "=r"(r0), "=r"(r1), "=r"(r2), "=r"(r3) : "r"(addr));
}

#define CP_ASYNC16(s, g) \
    asm volatile("cp.async.cg.shared.global [%0], [%1], 16;" :: "r"(s), "l"(g))
#define CP_COMMIT() asm volatile("cp.async.commit_group;")
#define CP_WAIT0()  asm volatile("cp.async.wait_group 0;")

// ---------------------------------------------------------------------------
// convert: fp32 inputs -> fp16 scratch; Jt[h][e][d] = lam * J[h][d][e]
// ---------------------------------------------------------------------------
__global__ void convert_kernel(
    const float* __restrict__ x,
    const float* __restrict__ Wq, const float* __restrict__ Wk,
    const float* __restrict__ Wv, const float* __restrict__ Wo,
    const float* __restrict__ J,  const float* __restrict__ lam_p)
{
    const int g = blockIdx.x * blockDim.x + threadIdx.x;
    const int T = gridDim.x * blockDim.x;

    #define CVT4(dst, src, n4)                                                  \
        for (int i = g; i < (n4); i += T) {                                     \
            float4 v = reinterpret_cast<const float4*>(src)[i];                 \
            __half2* o = reinterpret_cast<__half2*>(dst);                       \
            o[2*i]   = __floats2half2_rn(v.x, v.y);                             \
            o[2*i+1] = __floats2half2_rn(v.z, v.w);                             \
        }
    CVT4(g_xh,  x,  (NB*S_LEN*D_MODEL)/4)
    CVT4(g_Wqh, Wq, (D_MODEL*D_MODEL)/4)
    CVT4(g_Wkh, Wk, (D_MODEL*D_MODEL)/4)
    CVT4(g_Wvh, Wv, (D_MODEL*D_MODEL)/4)
    CVT4(g_Woh, Wo, (D_MODEL*D_MODEL)/4)
    #undef CVT4

    const float lam = lam_p[0];
    for (int i = g; i < NH * HD * HD; i += T) {
        const int h = i >> 12, rem = i & 4095, e = rem >> 6, d = rem & 63;
        g_Jth[i] = __float2half(lam * J[(h << 12) + (d << 6) + e]);
    }
}

// ---------------------------------------------------------------------------
// Shared fp16 GEMM mainloop: C[128x128] = A[128xK] * W[128xK]^T (K=1024).
// cp.async double-buffered, ldmatrix fragments. 256 threads, warp 64x32.
// ---------------------------------------------------------------------------
__device__ __forceinline__ void mainloop_f16(
    const __half* __restrict__ Ag, const __half* __restrict__ Wg,
    uint32_t saA, uint32_t saW,       // smem u32 base addrs of SA/SW (2 bufs each)
    int m0, int n0, int tid, int wm, int wn, int lane,
    float acc[4][4][4])
{
    const int mat = lane >> 3, r8 = lane & 7;
    // staging: 512 16B-chunks per matrix, 2 per thread
    const int crow = tid >> 2, ccc = (tid & 3) * 8;
    const size_t aG0 = (size_t)(m0 + crow)      * D_MODEL + ccc;
    const size_t aG1 = (size_t)(m0 + 64 + crow) * D_MODEL + ccc;
    const size_t wG0 = (size_t)(n0 + crow)      * D_MODEL + ccc;
    const size_t wG1 = (size_t)(n0 + 64 + crow) * D_MODEL + ccc;
    const uint32_t s0 = (crow * 40 + ccc) * 2;
    const uint32_t s1 = ((64 + crow) * 40 + ccc) * 2;

    const int aoff = ((mat & 1) * 8 + r8) * 40 + (mat >> 1) * 8;  // A frag offsets
    const int boff = ((mat >> 1) * 8 + r8) * 40 + (mat & 1) * 8;  // B frag offsets

    // prologue
    {
        CP_ASYNC16(saA + s0, Ag + aG0);
        CP_ASYNC16(saA + s1, Ag + aG1);
        CP_ASYNC16(saW + s0, Wg + wG0);
        CP_ASYNC16(saW + s1, Wg + wG1);
        CP_COMMIT();
    }

    for (int kt = 0; kt < 32; kt++) {
        const int buf = kt & 1;
        CP_WAIT0();
        __syncthreads();
        if (kt < 31) {
            const int go = (kt + 1) * 32;
            const uint32_t sb = (uint32_t)(buf ^ 1) * 5120 * 2;
            CP_ASYNC16(saA + sb + s0, Ag + aG0 + go);
            CP_ASYNC16(saA + sb + s1, Ag + aG1 + go);
            CP_ASYNC16(saW + sb + s0, Wg + wG0 + go);
            CP_ASYNC16(saW + sb + s1, Wg + wG1 + go);
            CP_COMMIT();
        }
        const uint32_t ab = saA + (uint32_t)buf * 5120 * 2;
        const uint32_t wb = saW + (uint32_t)buf * 5120 * 2;
        #pragma unroll
        for (int ks = 0; ks < 32; ks += 16) {
            uint32_t af[4][4], bf[4][2];
            #pragma unroll
            for (int mt = 0; mt < 4; mt++)
                ldsm_x4(af[mt][0], af[mt][1], af[mt][2], af[mt][3],
                        ab + (uint32_t)(((wm + mt * 16) * 40 + aoff + ks) * 2));
            #pragma unroll
            for (int ntp = 0; ntp < 2; ntp++) {
                uint32_t b0, b1, b2, b3;
                ldsm_x4(b0, b1, b2, b3,
                        wb + (uint32_t)(((wn + ntp * 16) * 40 + boff + ks) * 2));
                bf[2*ntp][0]   = b0; bf[2*ntp][1]   = b1;
                bf[2*ntp+1][0] = b2; bf[2*ntp+1][1] = b3;
            }
            #pragma unroll
            for (int mt = 0; mt < 4; mt++)
                #pragma unroll
                for (int nt = 0; nt < 4; nt++)
                    mma_f16(acc[mt][nt], af[mt], bf[nt]);
        }
    }
}

// ---------------------------------------------------------------------------
// QKV GEMM: z = 0 (Q + J-epilogue), 1 (K + tanh), 2 (V).
// dyn smem: [0, 20480) halves = SA|SW double buffers; T overlays [0,17408);
//           [20480, 29696) = Jt tile (2 heads x 64 x 72).
// ---------------------------------------------------------------------------
__global__ __launch_bounds__(256) void gemm_qkv(
    const __half* __restrict__ Ag,
    const __half* __restrict__ Wqh, const __half* __restrict__ Wkh,
    const __half* __restrict__ Wvh,
    const float* __restrict__ bq, const float* __restrict__ bk,
    const float* __restrict__ bv,
    const __half* __restrict__ Jtg,
    __half* __restrict__ Qh, __half* __restrict__ Kh, __half* __restrict__ Vh)
{
    extern __shared__ __half dsm[];
    __half* SA  = dsm;             // 2 x 5120
    __half* SW  = dsm + 10240;     // 2 x 5120
    __half* T   = dsm;             // 128 x 136 (overlay, used post-mainloop)
    __half* JtS = dsm + 20480;     // 2 x 64 x 72

    const int z    = blockIdx.z;
    const int tid  = threadIdx.x;
    const int lane = tid & 31;
    const int wid  = tid >> 5;
    const int m0   = blockIdx.y * 128;
    const int n0   = blockIdx.x * 128;
    const int wm   = (wid & 1) * 64;
    const int wn   = (wid >> 1) * 32;
    const int r    = lane >> 2;
    const int q    = lane & 3;
    const int mat  = lane >> 3, r8 = lane & 7;

    const __half* Wg = (z == 0) ? Wqh : (z == 1) ? Wkh : Wvh;
    const float* bias = (z == 0) ? bq : (z == 1) ? bk : bv;

    // Jt tile for this block's 2 heads (z==0 only)
    if (z == 0) {
        const int h0 = blockIdx.x * 2;
        for (int i = tid; i < 1024; i += 256) {       // 16B chunks
            const int row = i >> 3, cc = (i & 7) * 8;
            const int hh = row >> 6, e = row & 63;
            const uint4 v = *reinterpret_cast<const uint4*>(
                Jtg + ((size_t)(h0 + hh) << 12) + (e << 6) + cc);
            *reinterpret_cast<uint4*>(&JtS[(hh * 64 + e) * 72 + cc]) = v;
        }
    }

    float acc[4][4][4];
    #pragma unroll
    for (int i = 0; i < 4; i++)
        #pragma unroll
        for (int j = 0; j < 4; j++)
            #pragma unroll
            for (int e = 0; e < 4; e++) acc[i][j][e] = 0.f;

    mainloop_f16(Ag, Wg, smaddr(SA), smaddr(SW), m0, n0, tid, wm, wn, lane, acc);

    if (z == 0) __syncthreads();   // protect SA/SW before T overlay writes

    // epilogue
    #pragma unroll
    for (int mt = 0; mt < 4; mt++) {
        #pragma unroll
        for (int nt = 0; nt < 4; nt++) {
            const int rl0 = wm + mt * 16 + r;
            const int cl  = wn + nt * 8 + 2 * q;
            const float2 bb = *reinterpret_cast<const float2*>(&bias[n0 + cl]);
            #pragma unroll
            for (int hh = 0; hh < 2; hh++) {
                const int rl = rl0 + hh * 8;
                const int rw = m0 + rl;
                const float v0 = acc[mt][nt][hh * 2]     + bb.x;
                const float v1 = acc[mt][nt][hh * 2 + 1] + bb.y;
                const int b = rw >> 11, s = rw & 2047;
                const int cg = n0 + cl;
                const int h = cg >> 6, hd = cg & 63;
                const size_t base = ((size_t)((b << 4) + h) * S_LEN + s);
                if (z == 0) {
                    *reinterpret_cast<__half2*>(&Qh[base * DQK + hd]) =
                        __floats2half2_rn(v0 * 0.125f, v1 * 0.125f);
                    *reinterpret_cast<__half2*>(&T[rl * 136 + cl]) =
                        __floats2half2_rn(tanhf(v0), tanhf(v1));
                } else if (z == 1) {
                    *reinterpret_cast<__half2*>(&Kh[base * DQK + hd]) =
                        __floats2half2_rn(v0, v1);
                    *reinterpret_cast<__half2*>(&Kh[base * DQK + 64 + hd]) =
                        __floats2half2_rn(tanhf(v0), tanhf(v1));
                } else {
                    *reinterpret_cast<__half2*>(&Vh[base * HD + hd]) =
                        __floats2half2_rn(v0, v1);
                }
            }
        }
    }

    if (z != 0) return;

    // J-epilogue: QJ[128x64 per head] = T[:, head] @ Jt[head]^T (k = 64)
    __syncthreads();
    const uint32_t tB  = smaddr(T);
    const uint32_t jB  = smaddr(JtS);
    const int aoffT = ((mat & 1) * 8 + r8) * 136 + (mat >> 1) * 8;
    const int boffJ = ((mat >> 1) * 8 + r8) * 72  + (mat & 1) * 8;

    #pragma unroll
    for (int hh2 = 0; hh2 < 2; hh2++) {
        float a2[8][4];
        #pragma unroll
        for (int nt = 0; nt < 8; nt++)
            #pragma unroll
            for (int e = 0; e < 4; e++) a2[nt][e] = 0.f;

        #pragma unroll
        for (int ks = 0; ks < 4; ks++) {
            uint32_t af[4];
            ldsm_x4(af[0], af[1], af[2], af[3],
                    tB + (uint32_t)((wid * 16 * 136 + aoffT + hh2 * 64 + ks * 16) * 2));
            #pragma unroll
            for (int ntp = 0; ntp < 4; ntp++) {
                uint32_t b0, b1, b2, b3;
                ldsm_x4(b0, b1, b2, b3,
                        jB + (uint32_t)((hh2 * 64 * 72 + ntp * 16 * 72 + boffJ + ks * 16) * 2));
                uint32_t bf0[2] = {b0, b1}, bf1[2] = {b2, b3};
                mma_f16(a2[2*ntp],   af, bf0);
                mma_f16(a2[2*ntp+1], af, bf1);
            }
        }

        const int hgl = blockIdx.x * 2 + hh2;
        #pragma unroll
        for (int nt = 0; nt < 8; nt++) {
            const int e0 = nt * 8 + 2 * q;
            #pragma unroll
            for (int hh = 0; hh < 2; hh++) {
                const int rw = m0 + wid * 16 + r + hh * 8;
                const int b = rw >> 11, s = rw & 2047;
                const size_t base = ((size_t)((b << 4) + hgl) * S_LEN + s);
                *reinterpret_cast<__half2*>(&Qh[base * DQK + 64 + e0]) =
                    __floats2half2_rn(a2[nt][hh * 2], a2[nt][hh * 2 + 1]);
            }
        }
    }
}

// ---------------------------------------------------------------------------
// Output GEMM: out[4096x1024] fp32 = attn_h @ Wo^T + bo
// ---------------------------------------------------------------------------
__global__ __launch_bounds__(256) void gemm_out(
    const __half* __restrict__ Ag, const __half* __restrict__ Wg,
    const float* __restrict__ bias, float* __restrict__ C)
{
    extern __shared__ __half dsm[];
    __half* SA = dsm;
    __half* SW = dsm + 10240;

    const int tid  = threadIdx.x;
    const int lane = tid & 31;
    const int wid  = tid >> 5;
    const int m0   = blockIdx.y * 128;
    const int n0   = blockIdx.x * 128;
    const int wm   = (wid & 1) * 64;
    const int wn   = (wid >> 1) * 32;
    const int r    = lane >> 2;
    const int q    = lane & 3;

    float acc[4][4][4];
    #pragma unroll
    for (int i = 0; i < 4; i++)
        #pragma unroll
        for (int j = 0; j < 4; j++)
            #pragma unroll
            for (int e = 0; e < 4; e++) acc[i][j][e] = 0.f;

    mainloop_f16(Ag, Wg, smaddr(SA), smaddr(SW), m0, n0, tid, wm, wn, lane, acc);

    #pragma unroll
    for (int mt = 0; mt < 4; mt++) {
        #pragma unroll
        for (int nt = 0; nt < 4; nt++) {
            const int rw0 = m0 + wm + mt * 16 + r;
            const int cg  = n0 + wn + nt * 8 + 2 * q;
            const float2 bb = *reinterpret_cast<const float2*>(&bias[cg]);
            #pragma unroll
            for (int hh = 0; hh < 2; hh++) {
                const int rw = rw0 + hh * 8;
                *reinterpret_cast<float2*>(&C[(size_t)rw * D_MODEL + cg]) =
                    make_float2(acc[mt][nt][hh * 2] + bb.x,
                                acc[mt][nt][hh * 2 + 1] + bb.y);
            }
        }
    }
}

// ---------------------------------------------------------------------------
// Causal flash attention, fp16 mma + ldmatrix. BR=128, BC=64, 256 threads.
// ---------------------------------------------------------------------------
__global__ __launch_bounds__(256) void flash_f16(
    const __half* __restrict__ Qh, const __half* __restrict__ Kh,
    const __half* __restrict__ Vh, __half* __restrict__ Out)
{
    __shared__ __align__(16) __half Ks[64 * 136];
    __shared__ __align__(16) __half Vs[64 * 72];     // [d][j]

    const int bh   = blockIdx.y;
    const int r0   = (int)(gridDim.x - 1 - blockIdx.x) * 128;
    const int tid  = threadIdx.x;
    const int lane = tid & 31;
    const int wid  = tid >> 5;
    const int slab = wid * 16;
    const int r    = lane >> 2;
    const int q    = lane & 3;
    const int lr8  = lane & 7, lm = lane >> 3;

    const __half* Qb = Qh + (size_t)bh * S_LEN * DQK;
    const __half* Kb = Kh + (size_t)bh * S_LEN * DQK;
    const __half* Vb = Vh + (size_t)bh * S_LEN * HD;
    const uint32_t ksB = smaddr(Ks);
    const uint32_t vsB = smaddr(Vs);

    // Q fragments -> registers
    uint32_t qf[8][4];
    {
        const uint32_t* Qw = reinterpret_cast<const uint32_t*>(Qb);
        const int rowA = (r0 + slab + r) * 64;
        #pragma unroll
        for (int ks = 0; ks < 8; ks++) {
            const int c = ks * 8 + q;
            qf[ks][0] = Qw[rowA + c];
            qf[ks][1] = Qw[rowA + 512 + c];
            qf[ks][2] = Qw[rowA + c + 4];
            qf[ks][3] = Qw[rowA + 512 + c + 4];
        }
    }

    float m[2] = {-1e30f, -1e30f};
    float l[2] = {0.f, 0.f};
    float O[8][4];
    #pragma unroll
    for (int nt = 0; nt < 8; nt++)
        #pragma unroll
        for (int e = 0; e < 4; e++) O[nt][e] = 0.f;

    const int ntiles = (r0 >> 6) + 2;
    for (int t = 0; t < ntiles; t++) {
        const int c0 = t * 64;
        __syncthreads();
        {
            const uint4* src = reinterpret_cast<const uint4*>(Kb + (size_t)c0 * DQK);
            for (int i = tid; i < 1024; i += 256) {
                const int rr = i >> 4, g = i & 15;
                *reinterpret_cast<uint4*>(&Ks[rr * 136 + g * 8]) = src[rr * 16 + g];
            }
        }
        {
            const uint2* src = reinterpret_cast<const uint2*>(Vb + (size_t)c0 * HD);
            for (int i = tid; i < 1024; i += 256) {
                const int rr = i >> 4, g = i & 15;
                uint2 v = src[rr * 16 + g];
                const __half* hp = reinterpret_cast<const __half*>(&v);
                const int d0 = g * 4;
                #pragma unroll
                for (int c = 0; c < 4; c++)
                    Vs[(d0 + c) * 72 + rr] = hp[c];
            }
        }
        __syncthreads();

        if (c0 <= r0 + slab + 15) {
            // S = Q' K'^T
            float s[8][4];
            #pragma unroll
            for (int nt = 0; nt < 8; nt++)
                #pragma unroll
                for (int e = 0; e < 4; e++) s[nt][e] = 0.f;

            #pragma unroll
            for (int nt = 0; nt < 8; nt++) {
                #pragma unroll
                for (int kc = 0; kc < 4; kc++) {
                    uint32_t b0, b1, b2, b3;
                    ldsm_x4(b0, b1, b2, b3,
                            ksB + (uint32_t)(((nt * 8 + lr8) * 136 + kc * 32 + lm * 8) * 2));
                    uint32_t bf0[2] = {b0, b1}, bf1[2] = {b2, b3};
                    mma_f16(s[nt], qf[kc * 2],     bf0);
                    mma_f16(s[nt], qf[kc * 2 + 1], bf1);
                }
            }

            if (c0 + 63 > r0 + slab) {
                #pragma unroll
                for (int nt = 0; nt < 8; nt++)
                    #pragma unroll
                    for (int e = 0; e < 4; e++) {
                        const int gr = r0 + slab + r + (e >> 1) * 8;
                        const int gc = c0 + nt * 8 + 2 * q + (e & 1);
                        if (gc > gr) s[nt][e] = -1e30f;
                    }
            }

            #pragma unroll
            for (int half = 0; half < 2; half++) {
                float mx = -1e30f;
                #pragma unroll
                for (int nt = 0; nt < 8; nt++)
                    mx = fmaxf(mx, fmaxf(s[nt][half * 2], s[nt][half * 2 + 1]));
                mx = fmaxf(mx, __shfl_xor_sync(0xffffffffu, mx, 1));
                mx = fmaxf(mx, __shfl_xor_sync(0xffffffffu, mx, 2));
                const float mn = fmaxf(m[half], mx);
                const float corr = __expf(m[half] - mn);
                m[half] = mn;
                float rs = 0.f;
                #pragma unroll
                for (int nt = 0; nt < 8; nt++) {
                    const float p0 = __expf(s[nt][half * 2]     - mn);
                    const float p1 = __expf(s[nt][half * 2 + 1] - mn);
                    s[nt][half * 2]     = p0;
                    s[nt][half * 2 + 1] = p1;
                    rs += p0 + p1;
                }
                rs += __shfl_xor_sync(0xffffffffu, rs, 1);
                rs += __shfl_xor_sync(0xffffffffu, rs, 2);
                l[half] = l[half] * corr + rs;
                #pragma unroll
                for (int nt = 0; nt < 8; nt++) {
                    O[nt][half * 2]     *= corr;
                    O[nt][half * 2 + 1] *= corr;
                }
            }

            // P fragments (C->A identity), then O += P V
            uint32_t ap[4][4];
            #pragma unroll
            for (int j = 0; j < 4; j++) {
                ap[j][0] = packh2(s[2*j][0],   s[2*j][1]);
                ap[j][1] = packh2(s[2*j][2],   s[2*j][3]);
                ap[j][2] = packh2(s[2*j+1][0], s[2*j+1][1]);
                ap[j][3] = packh2(s[2*j+1][2], s[2*j+1][3]);
            }
            #pragma unroll
            for (int nt = 0; nt < 8; nt++) {
                #pragma unroll
                for (int jc = 0; jc < 2; jc++) {
                    uint32_t b0, b1, b2, b3;
                    ldsm_x4(b0, b1, b2, b3,
                            vsB + (uint32_t)(((nt * 8 + lr8) * 72 + jc * 32 + lm * 8) * 2));
                    uint32_t bf0[2] = {b0, b1}, bf1[2] = {b2, b3};
                    mma_f16(O[nt], ap[jc * 2],     bf0);
                    mma_f16(O[nt], ap[jc * 2 + 1], bf1);
                }
            }
        }
    }

    // epilogue (fp16 out)
    const int b = bh >> 4, h = bh & 15;
    #pragma unroll
    for (int half = 0; half < 2; half++) {
        const float inv = 1.f / l[half];
        const int gr = r0 + slab + r + half * 8;
        #pragma unroll
        for (int nt = 0; nt < 8; nt++) {
            const int d0 = nt * 8 + 2 * q;
            *reinterpret_cast<__half2*>(
                Out + ((size_t)(b * S_LEN + gr)) * D_MODEL + h * HD + d0) =
                __floats2half2_rn(O[nt][half * 2] * inv, O[nt][half * 2 + 1] * inv);
        }
    }
}

// ---------------------------------------------------------------------------
extern "C" void kernel_launch(void* const* d_in, const int* in_sizes, int n_in,
                              void* d_out, int out_size)
{
    const float* x   = (const float*)d_in[0];
    const float* Wq  = (const float*)d_in[1];
    const float* bq  = (const float*)d_in[2];
    const float* Wk  = (const float*)d_in[3];
    const float* bk  = (const float*)d_in[4];
    const float* Wv  = (const float*)d_in[5];
    const float* bv  = (const float*)d_in[6];
    const float* Wo  = (const float*)d_in[7];
    const float* bo  = (const float*)d_in[8];
    const float* J   = (const float*)d_in[9];
    const float* lam = (const float*)d_in[10];
    float* out = (float*)d_out;

    __half *xh, *wqh, *wkh, *wvh, *woh, *jth, *qh, *kh, *vh, *ah;
    cudaGetSymbolAddress((void**)&xh,  g_xh);
    cudaGetSymbolAddress((void**)&wqh, g_Wqh);
    cudaGetSymbolAddress((void**)&wkh, g_Wkh);
    cudaGetSymbolAddress((void**)&wvh, g_Wvh);
    cudaGetSymbolAddress((void**)&woh, g_Woh);
    cudaGetSymbolAddress((void**)&jth, g_Jth);
    cudaGetSymbolAddress((void**)&qh,  g_Qh);
    cudaGetSymbolAddress((void**)&kh,  g_Kh);
    cudaGetSymbolAddress((void**)&vh,  g_Vh);
    cudaGetSymbolAddress((void**)&ah,  g_attnh);

    convert_kernel<<<592, 256>>>(x, Wq, Wk, Wv, Wo, J, lam);

    const int SM_QKV = (20480 + 9216) * 2;   // 59392 B
    const int SM_OUT = 20480 * 2;            // 40960 B
    cudaFuncSetAttribute(gemm_qkv, cudaFuncAttributeMaxDynamicSharedMemorySize, SM_QKV);
    cudaFuncSetAttribute(gemm_out, cudaFuncAttributeMaxDynamicSharedMemorySize, SM_OUT);

    gemm_qkv<<<dim3(8, 32, 3), 256, SM_QKV>>>(xh, wqh, wkh, wvh,
                                              bq, bk, bv, jth, qh, kh, vh);

    flash_f16<<<dim3(S_LEN / 128, BHN), 256>>>(qh, kh, vh, ah);

    gemm_out<<<dim3(8, 32), 256, SM_OUT>>>(ah, woh, bo, out);
}